// round 11
// baseline (speedup 1.0000x reference)
#include <cuda_runtime.h>
#include <cuda_fp16.h>
#include <cstdio>
#include <cstdlib>
#include <cstdint>
#include <cmath>

#define Nn   100000
#define Ee   1600000
#define INF  128
#define Hd   64
#define Ll   8
#define OUTD 40

// ---------------- scratch (static device globals; no allocation) ----------------
__device__ int   g_deg[Nn];
__device__ float g_dis[Nn];
__device__ int   g_rowptr[Nn + 1];
__device__ int   g_cursor[Nn];
__device__ __align__(16) int2   g_ew[Ee];                 // {src, float_bits(norm)}
__device__ int   g_bsum[128];
__device__ __align__(16) __half g_tmp[(size_t)Nn * Hd];   // h @ W (fp16, gather payload)
__device__ __align__(16) float  g_h[(size_t)Nn * Hd];     // layer output (fp32)
__device__ int   g_is64;

// packed f32x2 FMA (Blackwell sm_100+): d = a*b + d, lanewise on 2 packed fp32
__device__ __forceinline__ void ffma2(uint64_t& d, uint64_t a, uint64_t b) {
    asm("fma.rn.f32x2 %0, %1, %2, %3;" : "=l"(d) : "l"(a), "l"(b), "l"(d));
}
__device__ __forceinline__ float f2lo(uint64_t v) { return __uint_as_float((unsigned)(v)); }
__device__ __forceinline__ float f2hi(uint64_t v) { return __uint_as_float((unsigned)(v >> 32)); }

// ---------------- dtype probe: int64 vs int32 edge_index ----------------
__global__ void k_detect(const unsigned int* __restrict__ p) {
    __shared__ unsigned int s;
    if (threadIdx.x == 0) s = 0u;
    __syncthreads();
    unsigned int v = 0u;
    for (int e = threadIdx.x; e < 2048; e += 256) v |= p[2 * e + 1];
    atomicOr(&s, v);
    __syncthreads();
    if (threadIdx.x == 0) g_is64 = (s == 0u) ? 1 : 0;
}
__device__ __forceinline__ int ld_src(const int* p, int e) {
    return g_is64 ? p[2 * e] : p[e];
}
__device__ __forceinline__ int ld_dst(const int* p, int e) {
    return g_is64 ? p[2 * Ee + 2 * e] : p[Ee + e];
}

// ---------------- degree ----------------
__global__ void k_count(const int* __restrict__ ei) {
    int e = blockIdx.x * 256 + threadIdx.x;
    if (e < Ee) atomicAdd(&g_deg[ld_dst(ei, e)], 1);
}

// ---------------- CSR build: exclusive scan of deg (+ dis folded in) ----------------
__global__ void k_scan_block() {
    __shared__ int s[1024];
    int i = blockIdx.x * 1024 + threadIdx.x;
    int v = (i < Nn) ? g_deg[i] : 0;
    if (i < Nn) g_dis[i] = rsqrtf((float)(v + 1));  // +1 self loop
    s[threadIdx.x] = v;
    __syncthreads();
    for (int off = 1; off < 1024; off <<= 1) {
        int t = (threadIdx.x >= off) ? s[threadIdx.x - off] : 0;
        __syncthreads();
        s[threadIdx.x] += t;
        __syncthreads();
    }
    if (i < Nn) g_rowptr[i] = s[threadIdx.x] - v;
    if (threadIdx.x == 1023) g_bsum[blockIdx.x] = s[1023];
}
__global__ void k_scan_bsum(int nb) {
    __shared__ int s[128];
    int v = (threadIdx.x < nb) ? g_bsum[threadIdx.x] : 0;
    s[threadIdx.x] = v;
    __syncthreads();
    for (int off = 1; off < 128; off <<= 1) {
        int t = (threadIdx.x >= off) ? s[threadIdx.x - off] : 0;
        __syncthreads();
        s[threadIdx.x] += t;
        __syncthreads();
    }
    if (threadIdx.x < nb) g_bsum[threadIdx.x] = s[threadIdx.x] - v;
}
__global__ void k_add_off() {
    int i = blockIdx.x * 1024 + threadIdx.x;
    if (i < Nn) {
        int r = g_rowptr[i] + g_bsum[blockIdx.x];
        g_rowptr[i] = r;
        g_cursor[i] = r;
    }
    if (i == 0) g_rowptr[Nn] = Ee;
}
__global__ void k_fill(const int* __restrict__ ei) {
    int e = blockIdx.x * 256 + threadIdx.x;
    if (e >= Ee) return;
    int s = ld_src(ei, e);
    int d = ld_dst(ei, e);
    int p = atomicAdd(&g_cursor[d], 1);
    g_ew[p] = make_int2(s, __float_as_int(g_dis[s] * g_dis[d]));
}

// ---------------- GEMM0: tmp[fp16] = x[N,128] @ W0[128,64]  (f32x2 path) ----------------
__global__ void k_gemm0(const float* __restrict__ A, const float* __restrict__ B,
                        __half2* __restrict__ C) {
    constexpr int K = 128, KT = 32;
    __shared__ float sAd[128][2 * KT + 2];  // duplicated (a,a) pairs
    __shared__ float sB[KT][64];
    const int row0 = blockIdx.x * 128;
    const int tid = threadIdx.x, tr = tid >> 4, tc = tid & 15;
    uint64_t acc[8][2];
#pragma unroll
    for (int i = 0; i < 8; i++) { acc[i][0] = 0ull; acc[i][1] = 0ull; }

    for (int k0 = 0; k0 < K; k0 += KT) {
#pragma unroll
        for (int t = 0; t < 4; t++) {
            int fi = tid + t * 256;
            int r = fi >> 3, c4 = fi & 7;
            float4 v = make_float4(0.f, 0.f, 0.f, 0.f);
            if (row0 + r < Nn)
                v = *(const float4*)&A[(size_t)(row0 + r) * K + k0 + c4 * 4];
            *(float2*)&sAd[r][2 * (c4 * 4 + 0)] = make_float2(v.x, v.x);
            *(float2*)&sAd[r][2 * (c4 * 4 + 1)] = make_float2(v.y, v.y);
            *(float2*)&sAd[r][2 * (c4 * 4 + 2)] = make_float2(v.z, v.z);
            *(float2*)&sAd[r][2 * (c4 * 4 + 3)] = make_float2(v.w, v.w);
        }
#pragma unroll
        for (int t = 0; t < 8; t++) {
            int fi = tid + t * 256;
            sB[fi >> 6][fi & 63] = B[(k0 + (fi >> 6)) * 64 + (fi & 63)];
        }
        __syncthreads();
#pragma unroll
        for (int kk = 0; kk < KT; kk++) {
            uint64_t b0 = *(const uint64_t*)&sB[kk][2 * tc];
            uint64_t b1 = *(const uint64_t*)&sB[kk][32 + 2 * tc];
#pragma unroll
            for (int i = 0; i < 8; i++) {
                uint64_t a2 = *(const uint64_t*)&sAd[tr + 16 * i][2 * kk];
                ffma2(acc[i][0], a2, b0);
                ffma2(acc[i][1], a2, b1);
            }
        }
        __syncthreads();
    }
#pragma unroll
    for (int i = 0; i < 8; i++) {
        int r = row0 + tr + 16 * i;
        if (r >= Nn) continue;
        C[(size_t)r * 32 + tc]      = __floats2half2_rn(f2lo(acc[i][0]), f2hi(acc[i][0]));
        C[(size_t)r * 32 + 16 + tc] = __floats2half2_rn(f2lo(acc[i][1]), f2hi(acc[i][1]));
    }
}

// ------- fused GEMM (f32x2): tmp[fp16] = h@W (64 cols) ; out (+)= h@LW (40 cols) -------
template <bool FIRST>
__global__ void k_gemm_fused(const float* __restrict__ A, const float* __restrict__ W,
                             const float* __restrict__ LW, __half2* __restrict__ C1,
                             float* __restrict__ out, const float* __restrict__ lin_b) {
    constexpr int K = 64, KT = 32, NC = 128;  // cols: 0..63 W, 64..103 LW, pad to 128
    __shared__ float sAd[128][2 * KT + 2];
    __shared__ float sB[KT][NC];
    const int row0 = blockIdx.x * 128;
    const int tid = threadIdx.x, tr = tid >> 4, tc = tid & 15;
    uint64_t acc[8][4];
#pragma unroll
    for (int i = 0; i < 8; i++)
#pragma unroll
        for (int j = 0; j < 4; j++) acc[i][j] = 0ull;

    for (int k0 = 0; k0 < K; k0 += KT) {
#pragma unroll
        for (int t = 0; t < 4; t++) {
            int fi = tid + t * 256;
            int r = fi >> 3, c4 = fi & 7;
            float4 v = make_float4(0.f, 0.f, 0.f, 0.f);
            if (row0 + r < Nn)
                v = *(const float4*)&A[(size_t)(row0 + r) * K + k0 + c4 * 4];
            *(float2*)&sAd[r][2 * (c4 * 4 + 0)] = make_float2(v.x, v.x);
            *(float2*)&sAd[r][2 * (c4 * 4 + 1)] = make_float2(v.y, v.y);
            *(float2*)&sAd[r][2 * (c4 * 4 + 2)] = make_float2(v.z, v.z);
            *(float2*)&sAd[r][2 * (c4 * 4 + 3)] = make_float2(v.w, v.w);
        }
        for (int fi = tid; fi < KT * NC; fi += 256) {
            int kk = fi >> 7, c = fi & 127;
            float v = 0.f;
            if (c < 64) v = W[(k0 + kk) * 64 + c];
            else if (c < 104) v = LW[(k0 + kk) * OUTD + (c - 64)];
            sB[kk][c] = v;
        }
        __syncthreads();
#pragma unroll
        for (int kk = 0; kk < KT; kk++) {
            uint64_t b0 = *(const uint64_t*)&sB[kk][2 * tc];
            uint64_t b1 = *(const uint64_t*)&sB[kk][32 + 2 * tc];
            uint64_t b2 = *(const uint64_t*)&sB[kk][64 + 2 * tc];
            uint64_t b3 = *(const uint64_t*)&sB[kk][96 + 2 * tc];
#pragma unroll
            for (int i = 0; i < 8; i++) {
                uint64_t a2 = *(const uint64_t*)&sAd[tr + 16 * i][2 * kk];
                ffma2(acc[i][0], a2, b0);
                ffma2(acc[i][1], a2, b1);
                ffma2(acc[i][2], a2, b2);
                ffma2(acc[i][3], a2, b3);
            }
        }
        __syncthreads();
    }
#pragma unroll
    for (int i = 0; i < 8; i++) {
        int r = row0 + tr + 16 * i;
        if (r >= Nn) continue;
        C1[(size_t)r * 32 + tc]      = __floats2half2_rn(f2lo(acc[i][0]), f2hi(acc[i][0]));
        C1[(size_t)r * 32 + 16 + tc] = __floats2half2_rn(f2lo(acc[i][1]), f2hi(acc[i][1]));
        // out cols from pair2: 2tc,2tc+1 (always <40); pair3: 32+2tc,33+2tc (valid tc<4)
        {
            int oc = 2 * tc;
            if (FIRST) {
                out[(size_t)r * OUTD + oc]     = f2lo(acc[i][2]) + lin_b[oc];
                out[(size_t)r * OUTD + oc + 1] = f2hi(acc[i][2]) + lin_b[oc + 1];
            } else {
                out[(size_t)r * OUTD + oc]     += f2lo(acc[i][2]);
                out[(size_t)r * OUTD + oc + 1] += f2hi(acc[i][2]);
            }
        }
        if (tc < 4) {
            int oc = 32 + 2 * tc;
            if (FIRST) {
                out[(size_t)r * OUTD + oc]     = f2lo(acc[i][3]) + lin_b[oc];
                out[(size_t)r * OUTD + oc + 1] = f2hi(acc[i][3]) + lin_b[oc + 1];
            } else {
                out[(size_t)r * OUTD + oc]     += f2lo(acc[i][3]);
                out[(size_t)r * OUTD + oc + 1] += f2hi(acc[i][3]);
            }
        }
    }
}

// ---------------- JK-only GEMM (last layer, f32x2): out += h @ lin_w[7] ----------------
__global__ void k_gemm_jk(const float* __restrict__ A, const float* __restrict__ B,
                          float* __restrict__ C) {
    constexpr int K = 64, KT = 32;
    __shared__ float sAd[128][2 * KT + 2];
    __shared__ float sB[KT][64];  // 40 cols padded to 64
    const int row0 = blockIdx.x * 128;
    const int tid = threadIdx.x, tr = tid >> 4, tc = tid & 15;
    uint64_t acc[8][2];
#pragma unroll
    for (int i = 0; i < 8; i++) { acc[i][0] = 0ull; acc[i][1] = 0ull; }

    for (int k0 = 0; k0 < K; k0 += KT) {
#pragma unroll
        for (int t = 0; t < 4; t++) {
            int fi = tid + t * 256;
            int r = fi >> 3, c4 = fi & 7;
            float4 v = make_float4(0.f, 0.f, 0.f, 0.f);
            if (row0 + r < Nn)
                v = *(const float4*)&A[(size_t)(row0 + r) * K + k0 + c4 * 4];
            *(float2*)&sAd[r][2 * (c4 * 4 + 0)] = make_float2(v.x, v.x);
            *(float2*)&sAd[r][2 * (c4 * 4 + 1)] = make_float2(v.y, v.y);
            *(float2*)&sAd[r][2 * (c4 * 4 + 2)] = make_float2(v.z, v.z);
            *(float2*)&sAd[r][2 * (c4 * 4 + 3)] = make_float2(v.w, v.w);
        }
#pragma unroll
        for (int t = 0; t < 8; t++) {
            int fi = tid + t * 256;
            int kk = fi >> 6, c = fi & 63;
            sB[kk][c] = (c < OUTD) ? B[(k0 + kk) * OUTD + c] : 0.f;
        }
        __syncthreads();
#pragma unroll
        for (int kk = 0; kk < KT; kk++) {
            uint64_t b0 = *(const uint64_t*)&sB[kk][2 * tc];
            uint64_t b1 = *(const uint64_t*)&sB[kk][32 + 2 * tc];
#pragma unroll
            for (int i = 0; i < 8; i++) {
                uint64_t a2 = *(const uint64_t*)&sAd[tr + 16 * i][2 * kk];
                ffma2(acc[i][0], a2, b0);
                ffma2(acc[i][1], a2, b1);
            }
        }
        __syncthreads();
    }
#pragma unroll
    for (int i = 0; i < 8; i++) {
        int r = row0 + tr + 16 * i;
        if (r >= Nn) continue;
        {
            int oc = 2 * tc;  // 0..31, always valid
            C[(size_t)r * OUTD + oc]     += f2lo(acc[i][0]);
            C[(size_t)r * OUTD + oc + 1] += f2hi(acc[i][0]);
        }
        if (tc < 4) {
            int oc = 32 + 2 * tc;  // 32..39
            C[(size_t)r * OUTD + oc]     += f2lo(acc[i][1]);
            C[(size_t)r * OUTD + oc + 1] += f2hi(acc[i][1]);
        }
    }
}

// ---------------- sparse aggregation: h = relu(A_hat * tmp + b), tmp fp16 ----------------
__global__ void k_aggregate(const float* __restrict__ bias) {
    int node = blockIdx.x * 8 + (threadIdx.x >> 5);
    if (node >= Nn) return;
    int lane = threadIdx.x & 31;
    const __half2* tp = (const __half2*)g_tmp;
    float ax = 0.f, ay = 0.f;
    int beg = g_rowptr[node], end = g_rowptr[node + 1];
    for (int j = beg; j < end; j++) {
        int2 e = __ldg(&g_ew[j]);
        float wt = __int_as_float(e.y);
        float2 v = __half22float2(tp[(size_t)e.x * 32 + lane]);
        ax += wt * v.x;
        ay += wt * v.y;
    }
    float d = g_dis[node];
    float sw = d * d;
    float2 v = __half22float2(tp[(size_t)node * 32 + lane]);
    ax += sw * v.x;
    ay += sw * v.y;
    ax += bias[2 * lane];
    ay += bias[2 * lane + 1];
    float2 r;
    r.x = fmaxf(ax, 0.f);
    r.y = fmaxf(ay, 0.f);
    *(float2*)&g_h[(size_t)node * Hd + 2 * lane] = r;
}

extern "C" void kernel_launch(void* const* d_in, const int* in_sizes, int n_in,
                              void* d_out, int out_size) {
    const float* x = nullptr;
    const float* W0 = nullptr;
    const float* Ws = nullptr;
    const float* bs = nullptr;
    const float* lin_w = nullptr;
    const float* lin_b = nullptr;
    const int*   ei = nullptr;
    for (int i = 0; i < n_in; i++) {
        switch (in_sizes[i]) {
            case 12800000: x     = (const float*)d_in[i]; break;
            case 8192:     W0    = (const float*)d_in[i]; break;
            case 28672:    Ws    = (const float*)d_in[i]; break;
            case 512:      bs    = (const float*)d_in[i]; break;
            case 20480:    lin_w = (const float*)d_in[i]; break;
            case 40:       lin_b = (const float*)d_in[i]; break;
            case 3200000:
            case 6400000:  ei    = (const int*)d_in[i];   break;
            default: break;
        }
    }
    if (!(x && W0 && Ws && bs && lin_w && lin_b && ei)) {
        x     = (const float*)d_in[0];
        W0    = (const float*)d_in[1];
        Ws    = (const float*)d_in[2];
        bs    = (const float*)d_in[3];
        lin_w = (const float*)d_in[4];
        lin_b = (const float*)d_in[5];
        ei    = (const int*)d_in[6];
    }
    float* out = (float*)d_out;

    // device-symbol addresses for host-side kernel args (R7 root cause)
    __half2* tmp_d = nullptr;
    float*   h_d   = nullptr;
    int*     deg_d = nullptr;
    cudaGetSymbolAddress((void**)&tmp_d, g_tmp);
    cudaGetSymbolAddress((void**)&h_d, g_h);
    cudaGetSymbolAddress((void**)&deg_d, g_deg);

    cudaStreamCaptureStatus cs = cudaStreamCaptureStatusNone;
    cudaError_t qe = cudaStreamIsCapturing((cudaStream_t)0, &cs);
    bool capturing = (qe != cudaSuccess) || (cs != cudaStreamCaptureStatusNone);
    if (qe != cudaSuccess) (void)cudaGetLastError();

    const int NB = (Nn + 1023) / 1024;      // 98
    const int GEMM_GRID = (Nn + 127) / 128; // 782
    const int AGG_GRID = (Nn + 7) / 8;

    k_detect<<<1, 256>>>((const unsigned int*)ei);
    cudaMemsetAsync(deg_d, 0, Nn * sizeof(int), 0);
    k_count<<<(Ee + 255) / 256, 256>>>(ei);
    k_scan_block<<<NB, 1024>>>();
    k_scan_bsum<<<1, 128>>>(NB);
    k_add_off<<<NB, 1024>>>();
    k_fill<<<(Ee + 255) / 256, 256>>>(ei);

    k_gemm0<<<GEMM_GRID, 256>>>(x, W0, tmp_d);
    for (int l = 0; l < Ll; l++) {
        k_aggregate<<<AGG_GRID, 256>>>(bs + l * Hd);
        if (l < Ll - 1) {
            if (l == 0)
                k_gemm_fused<true><<<GEMM_GRID, 256>>>(h_d, Ws + (size_t)l * Hd * Hd,
                                                       lin_w + (size_t)l * Hd * OUTD,
                                                       tmp_d, out, lin_b);
            else
                k_gemm_fused<false><<<GEMM_GRID, 256>>>(h_d, Ws + (size_t)l * Hd * Hd,
                                                        lin_w + (size_t)l * Hd * OUTD,
                                                        tmp_d, out, lin_b);
        } else {
            k_gemm_jk<<<GEMM_GRID, 256>>>(h_d, lin_w + (size_t)l * Hd * OUTD, out);
        }
    }

    // -------- zero-output tripwire (correctness call only; never during capture) --------
    if (!capturing) {
        static float ho[8];
        cudaMemcpyAsync(ho, out, 8 * sizeof(float), cudaMemcpyDeviceToHost, 0);
        cudaError_t qs = cudaErrorNotReady;
        for (long it = 0; it < 4000000000L; it++) {
            qs = cudaStreamQuery((cudaStream_t)0);
            if (qs != cudaErrorNotReady) break;
        }
        float mx = 0.f;
        for (int i = 0; i < 8; i++) mx = fmaxf(mx, fabsf(ho[i]));
        if (qs != cudaSuccess || mx < 1e-6f) {
            fprintf(stderr, "[diag] TRIPWIRE mx=%g q=%s out=%g %g %g %g\n", mx,
                    cudaGetErrorName(qs), ho[0], ho[1], ho[2], ho[3]);
            fflush(stderr);
            abort();
        }
    }
}

// round 12
// speedup vs baseline: 1.0184x; 1.0184x over previous
#include <cuda_runtime.h>
#include <cuda_fp16.h>
#include <cstdio>
#include <cstdlib>
#include <cstdint>
#include <cmath>

#define Nn   100000
#define Ee   1600000
#define INF  128
#define Hd   64
#define Ll   8
#define OUTD 40

// ---------------- scratch (static device globals; no allocation) ----------------
__device__ int   g_deg[Nn];
__device__ float g_dis[Nn];
__device__ int   g_rowptr[Nn + 1];
__device__ int   g_cursor[Nn];
__device__ __align__(16) int2   g_ew[Ee];                 // {src, float_bits(norm)}
__device__ int   g_bsum[128];
__device__ __align__(16) __half g_tmp[(size_t)Nn * Hd];   // h @ W (fp16, gather payload)
__device__ __align__(16) __half g_h[(size_t)Nn * Hd];     // layer output (fp16)
__device__ int   g_is64;

// ---------------- dtype probe: int64 vs int32 edge_index ----------------
__global__ void k_detect(const unsigned int* __restrict__ p) {
    __shared__ unsigned int s;
    if (threadIdx.x == 0) s = 0u;
    __syncthreads();
    unsigned int v = 0u;
    for (int e = threadIdx.x; e < 2048; e += 256) v |= p[2 * e + 1];
    atomicOr(&s, v);
    __syncthreads();
    if (threadIdx.x == 0) g_is64 = (s == 0u) ? 1 : 0;
}
__device__ __forceinline__ int ld_src(const int* p, int e) {
    return g_is64 ? p[2 * e] : p[e];
}
__device__ __forceinline__ int ld_dst(const int* p, int e) {
    return g_is64 ? p[2 * Ee + 2 * e] : p[Ee + e];
}

// ---------------- degree ----------------
__global__ void k_count(const int* __restrict__ ei) {
    int e = blockIdx.x * 256 + threadIdx.x;
    if (e < Ee) atomicAdd(&g_deg[ld_dst(ei, e)], 1);
}

// ---------------- CSR build: block scan of deg (+ dis folded in) ----------------
__global__ void k_scan_block() {
    __shared__ int s[1024];
    int i = blockIdx.x * 1024 + threadIdx.x;
    int v = (i < Nn) ? g_deg[i] : 0;
    if (i < Nn) g_dis[i] = rsqrtf((float)(v + 1));  // +1 self loop
    s[threadIdx.x] = v;
    __syncthreads();
    for (int off = 1; off < 1024; off <<= 1) {
        int t = (threadIdx.x >= off) ? s[threadIdx.x - off] : 0;
        __syncthreads();
        s[threadIdx.x] += t;
        __syncthreads();
    }
    if (i < Nn) g_rowptr[i] = s[threadIdx.x] - v;
    if (threadIdx.x == 1023) g_bsum[blockIdx.x] = s[1023];
}
// add_off with the bsum prefix computed per-block (merges old scan_bsum kernel)
__global__ void k_add_off() {
    __shared__ int sb[128];
    int t = threadIdx.x;
    if (t < 128) sb[t] = (t < (int)blockIdx.x) ? g_bsum[t] : 0;  // NB<=98<128
    __syncthreads();
    for (int off = 64; off > 0; off >>= 1) {
        if (t < off) sb[t] += sb[t + off];
        __syncthreads();
    }
    int base = sb[0];
    int i = blockIdx.x * 1024 + t;
    if (i < Nn) {
        int r = g_rowptr[i] + base;
        g_rowptr[i] = r;
        g_cursor[i] = r;
    }
    if (i == 0) g_rowptr[Nn] = Ee;
}
__global__ void k_fill(const int* __restrict__ ei) {
    int e = blockIdx.x * 256 + threadIdx.x;
    if (e >= Ee) return;
    int s = ld_src(ei, e);
    int d = ld_dst(ei, e);
    int p = atomicAdd(&g_cursor[d], 1);
    g_ew[p] = make_int2(s, __float_as_int(g_dis[s] * g_dis[d]));
}

// ---------------- GEMM0: tmp[fp16] = x[N,128] @ W0[128,64] ----------------
// 128-row tile, 256 thr (16x16), 8x4 acc; col map j -> 2*tc+(j&1)+32*(j>>1)
__global__ void k_gemm0(const float* __restrict__ A, const float* __restrict__ B,
                        __half2* __restrict__ C) {
    constexpr int K = 128, KT = 32;
    __shared__ float sA[128][KT + 1];
    __shared__ float sB[KT][64];
    const int row0 = blockIdx.x * 128;
    const int tid = threadIdx.x, tr = tid >> 4, tc = tid & 15;
    float acc[8][4];
#pragma unroll
    for (int i = 0; i < 8; i++)
#pragma unroll
        for (int j = 0; j < 4; j++) acc[i][j] = 0.f;

    for (int k0 = 0; k0 < K; k0 += KT) {
#pragma unroll
        for (int t = 0; t < 4; t++) {
            int fi = tid + t * 256;
            int r = fi >> 3, c4 = fi & 7;
            float4 v = make_float4(0.f, 0.f, 0.f, 0.f);
            if (row0 + r < Nn)
                v = *(const float4*)&A[(size_t)(row0 + r) * K + k0 + c4 * 4];
            sA[r][c4 * 4 + 0] = v.x; sA[r][c4 * 4 + 1] = v.y;
            sA[r][c4 * 4 + 2] = v.z; sA[r][c4 * 4 + 3] = v.w;
        }
#pragma unroll
        for (int t = 0; t < 8; t++) {
            int fi = tid + t * 256;
            sB[fi >> 6][fi & 63] = B[(k0 + (fi >> 6)) * 64 + (fi & 63)];
        }
        __syncthreads();
#pragma unroll
        for (int kk = 0; kk < KT; kk++) {
            float a[8], b[4];
#pragma unroll
            for (int i = 0; i < 8; i++) a[i] = sA[tr + 16 * i][kk];
#pragma unroll
            for (int j = 0; j < 4; j++) b[j] = sB[kk][2 * tc + (j & 1) + 32 * (j >> 1)];
#pragma unroll
            for (int i = 0; i < 8; i++)
#pragma unroll
                for (int j = 0; j < 4; j++) acc[i][j] += a[i] * b[j];
        }
        __syncthreads();
    }
#pragma unroll
    for (int i = 0; i < 8; i++) {
        int r = row0 + tr + 16 * i;
        if (r >= Nn) continue;
        C[(size_t)r * 32 + tc]      = __floats2half2_rn(acc[i][0], acc[i][1]);
        C[(size_t)r * 32 + 16 + tc] = __floats2half2_rn(acc[i][2], acc[i][3]);
    }
}

// ------- fused GEMM: tmp[fp16] = h@W (64) ; out (+)= h@LW (40); A is fp16 -------
template <bool FIRST>
__global__ void k_gemm_fused(const __half* __restrict__ A, const float* __restrict__ W,
                             const float* __restrict__ LW, __half2* __restrict__ C1,
                             float* __restrict__ out, const float* __restrict__ lin_b) {
    constexpr int K = 64, KT = 32, NC = 112;  // 104 cols padded to 112
    __shared__ float sA[128][KT + 1];
    __shared__ float sB[KT][NC];
    const int row0 = blockIdx.x * 128;
    const int tid = threadIdx.x, tr = tid >> 4, tc = tid & 15;
    const __half2* A2 = (const __half2*)A;
    float acc[8][7];
#pragma unroll
    for (int i = 0; i < 8; i++)
#pragma unroll
        for (int j = 0; j < 7; j++) acc[i][j] = 0.f;

    for (int k0 = 0; k0 < K; k0 += KT) {
        // A tile: 128 rows x 32 cols fp16 = 2048 half2, 8 per thread
#pragma unroll
        for (int t = 0; t < 8; t++) {
            int fi = tid + t * 256;
            int r = fi >> 4, c2 = fi & 15;
            float2 v = make_float2(0.f, 0.f);
            if (row0 + r < Nn)
                v = __half22float2(A2[(size_t)(row0 + r) * 32 + (k0 >> 1) + c2]);
            sA[r][2 * c2] = v.x;
            sA[r][2 * c2 + 1] = v.y;
        }
        // sB: 32 x 112  (cols 0..63 = W, 64..103 = LW, rest 0)
        for (int fi = tid; fi < KT * NC; fi += 256) {
            int kk = fi / NC, c = fi % NC;
            float v = 0.f;
            if (c < 64) v = W[(k0 + kk) * 64 + c];
            else if (c < 104) v = LW[(k0 + kk) * OUTD + (c - 64)];
            sB[kk][c] = v;
        }
        __syncthreads();
#pragma unroll
        for (int kk = 0; kk < KT; kk++) {
            float a[8], b[7];
#pragma unroll
            for (int i = 0; i < 8; i++) a[i] = sA[tr + 16 * i][kk];
#pragma unroll
            for (int j = 0; j < 4; j++) b[j] = sB[kk][2 * tc + (j & 1) + 32 * (j >> 1)];
#pragma unroll
            for (int j = 4; j < 7; j++) b[j] = sB[kk][64 + tc + 16 * (j - 4)];
#pragma unroll
            for (int i = 0; i < 8; i++)
#pragma unroll
                for (int j = 0; j < 7; j++) acc[i][j] += a[i] * b[j];
        }
        __syncthreads();
    }
#pragma unroll
    for (int i = 0; i < 8; i++) {
        int r = row0 + tr + 16 * i;
        if (r >= Nn) continue;
        C1[(size_t)r * 32 + tc]      = __floats2half2_rn(acc[i][0], acc[i][1]);
        C1[(size_t)r * 32 + 16 + tc] = __floats2half2_rn(acc[i][2], acc[i][3]);
#pragma unroll
        for (int j = 4; j < 7; j++) {
            int oc = tc + 16 * (j - 4);
            if (oc < OUTD) {
                if (FIRST) out[(size_t)r * OUTD + oc] = acc[i][j] + lin_b[oc];
                else       out[(size_t)r * OUTD + oc] += acc[i][j];
            }
        }
    }
}

// ---------------- JK-only GEMM (last layer): out += h @ lin_w[7]; A fp16 ----------------
__global__ void k_gemm_jk(const __half* __restrict__ A, const float* __restrict__ B,
                          float* __restrict__ C) {
    constexpr int K = 64, KT = 32;
    __shared__ float sA[128][KT + 1];
    __shared__ float sB[KT][64];
    const int row0 = blockIdx.x * 128;
    const int tid = threadIdx.x, tr = tid >> 4, tc = tid & 15;
    const __half2* A2 = (const __half2*)A;
    float acc[8][4];
#pragma unroll
    for (int i = 0; i < 8; i++)
#pragma unroll
        for (int j = 0; j < 4; j++) acc[i][j] = 0.f;

    for (int k0 = 0; k0 < K; k0 += KT) {
#pragma unroll
        for (int t = 0; t < 8; t++) {
            int fi = tid + t * 256;
            int r = fi >> 4, c2 = fi & 15;
            float2 v = make_float2(0.f, 0.f);
            if (row0 + r < Nn)
                v = __half22float2(A2[(size_t)(row0 + r) * 32 + (k0 >> 1) + c2]);
            sA[r][2 * c2] = v.x;
            sA[r][2 * c2 + 1] = v.y;
        }
#pragma unroll
        for (int t = 0; t < 8; t++) {
            int fi = tid + t * 256;
            int kk = fi >> 6, c = fi & 63;
            sB[kk][c] = (c < OUTD) ? B[(k0 + kk) * OUTD + c] : 0.f;
        }
        __syncthreads();
#pragma unroll
        for (int kk = 0; kk < KT; kk++) {
            float a[8], b[4];
#pragma unroll
            for (int i = 0; i < 8; i++) a[i] = sA[tr + 16 * i][kk];
#pragma unroll
            for (int j = 0; j < 4; j++) b[j] = sB[kk][tc + 16 * j];
#pragma unroll
            for (int i = 0; i < 8; i++)
#pragma unroll
                for (int j = 0; j < 4; j++) acc[i][j] += a[i] * b[j];
        }
        __syncthreads();
    }
#pragma unroll
    for (int i = 0; i < 8; i++) {
        int r = row0 + tr + 16 * i;
        if (r >= Nn) continue;
#pragma unroll
        for (int j = 0; j < 4; j++) {
            int c = tc + 16 * j;
            if (c < OUTD) C[(size_t)r * OUTD + c] += acc[i][j];
        }
    }
}

// ---------------- sparse aggregation: h[fp16] = relu(A_hat * tmp + b) ----------------
__global__ void k_aggregate(const float* __restrict__ bias) {
    int node = blockIdx.x * 8 + (threadIdx.x >> 5);
    if (node >= Nn) return;
    int lane = threadIdx.x & 31;
    const __half2* tp = (const __half2*)g_tmp;
    __half2* hp = (__half2*)g_h;
    float ax = 0.f, ay = 0.f;
    int beg = g_rowptr[node], end = g_rowptr[node + 1];
    for (int j = beg; j < end; j++) {
        int2 e = __ldg(&g_ew[j]);
        float wt = __int_as_float(e.y);
        float2 v = __half22float2(tp[(size_t)e.x * 32 + lane]);
        ax += wt * v.x;
        ay += wt * v.y;
    }
    float d = g_dis[node];
    float sw = d * d;
    float2 v = __half22float2(tp[(size_t)node * 32 + lane]);
    ax += sw * v.x;
    ay += sw * v.y;
    ax += bias[2 * lane];
    ay += bias[2 * lane + 1];
    hp[(size_t)node * 32 + lane] = __floats2half2_rn(fmaxf(ax, 0.f), fmaxf(ay, 0.f));
}

extern "C" void kernel_launch(void* const* d_in, const int* in_sizes, int n_in,
                              void* d_out, int out_size) {
    const float* x = nullptr;
    const float* W0 = nullptr;
    const float* Ws = nullptr;
    const float* bs = nullptr;
    const float* lin_w = nullptr;
    const float* lin_b = nullptr;
    const int*   ei = nullptr;
    for (int i = 0; i < n_in; i++) {
        switch (in_sizes[i]) {
            case 12800000: x     = (const float*)d_in[i]; break;
            case 8192:     W0    = (const float*)d_in[i]; break;
            case 28672:    Ws    = (const float*)d_in[i]; break;
            case 512:      bs    = (const float*)d_in[i]; break;
            case 20480:    lin_w = (const float*)d_in[i]; break;
            case 40:       lin_b = (const float*)d_in[i]; break;
            case 3200000:
            case 6400000:  ei    = (const int*)d_in[i];   break;
            default: break;
        }
    }
    if (!(x && W0 && Ws && bs && lin_w && lin_b && ei)) {
        x     = (const float*)d_in[0];
        W0    = (const float*)d_in[1];
        Ws    = (const float*)d_in[2];
        bs    = (const float*)d_in[3];
        lin_w = (const float*)d_in[4];
        lin_b = (const float*)d_in[5];
        ei    = (const int*)d_in[6];
    }
    float* out = (float*)d_out;

    // device-symbol addresses for host-side kernel args (R7 root cause)
    __half2* tmp_d = nullptr;
    __half*  h_d   = nullptr;
    int*     deg_d = nullptr;
    cudaGetSymbolAddress((void**)&tmp_d, g_tmp);
    cudaGetSymbolAddress((void**)&h_d, g_h);
    cudaGetSymbolAddress((void**)&deg_d, g_deg);

    cudaStreamCaptureStatus cs = cudaStreamCaptureStatusNone;
    cudaError_t qe = cudaStreamIsCapturing((cudaStream_t)0, &cs);
    bool capturing = (qe != cudaSuccess) || (cs != cudaStreamCaptureStatusNone);
    if (qe != cudaSuccess) (void)cudaGetLastError();

    const int NB = (Nn + 1023) / 1024;      // 98
    const int GEMM_GRID = (Nn + 127) / 128; // 782
    const int AGG_GRID = (Nn + 7) / 8;

    // Launch order puts k_gemm0 at slot 5 (ncu profiles the 5th launch) — it has
    // no dependency on the CSR-build chain, so this reorder is semantically free.
    k_detect<<<1, 256>>>((const unsigned int*)ei);                 // 1
    cudaMemsetAsync(deg_d, 0, Nn * sizeof(int), 0);                // 2
    k_count<<<(Ee + 255) / 256, 256>>>(ei);                        // 3
    k_scan_block<<<NB, 1024>>>();                                  // 4
    k_gemm0<<<GEMM_GRID, 256>>>(x, W0, tmp_d);                     // 5  <- profiled
    k_add_off<<<NB, 1024>>>();                                     // 6 (incl. bsum prefix)
    k_fill<<<(Ee + 255) / 256, 256>>>(ei);                         // 7

    for (int l = 0; l < Ll; l++) {
        k_aggregate<<<AGG_GRID, 256>>>(bs + l * Hd);
        if (l < Ll - 1) {
            if (l == 0)
                k_gemm_fused<true><<<GEMM_GRID, 256>>>(h_d, Ws + (size_t)l * Hd * Hd,
                                                       lin_w + (size_t)l * Hd * OUTD,
                                                       tmp_d, out, lin_b);
            else
                k_gemm_fused<false><<<GEMM_GRID, 256>>>(h_d, Ws + (size_t)l * Hd * Hd,
                                                        lin_w + (size_t)l * Hd * OUTD,
                                                        tmp_d, out, lin_b);
        } else {
            k_gemm_jk<<<GEMM_GRID, 256>>>(h_d, lin_w + (size_t)l * Hd * OUTD, out);
        }
    }

    // -------- zero-output tripwire (correctness call only; never during capture) --------
    if (!capturing) {
        static float ho[8];
        cudaMemcpyAsync(ho, out, 8 * sizeof(float), cudaMemcpyDeviceToHost, 0);
        cudaError_t qs = cudaErrorNotReady;
        for (long it = 0; it < 4000000000L; it++) {
            qs = cudaStreamQuery((cudaStream_t)0);
            if (qs != cudaErrorNotReady) break;
        }
        float mx = 0.f;
        for (int i = 0; i < 8; i++) mx = fmaxf(mx, fabsf(ho[i]));
        if (qs != cudaSuccess || mx < 1e-6f) {
            fprintf(stderr, "[diag] TRIPWIRE mx=%g q=%s out=%g %g %g %g\n", mx,
                    cudaGetErrorName(qs), ho[0], ho[1], ho[2], ho[3]);
            fflush(stderr);
            abort();
        }
    }
}

// round 13
// speedup vs baseline: 1.8748x; 1.8408x over previous
#include <cuda_runtime.h>
#include <cuda_fp16.h>
#include <cstdio>
#include <cstdlib>
#include <cstdint>
#include <cmath>

#define Nn   100000
#define Ee   1600000
#define Hd   64
#define Ll   8
#define OUTD 40

// ---------------- scratch (static device globals; no allocation) ----------------
__device__ int   g_deg[Nn];
__device__ float g_dis[Nn];
__device__ int   g_rowptr[Nn + 1];
__device__ int   g_cursor[Nn];
__device__ __align__(16) int2   g_ew[Ee];                    // {src, float_bits(norm)}
__device__ int   g_bsum[128];
__device__ __align__(16) __half g_x16[(size_t)Nn * 128];     // x in fp16
__device__ __align__(16) __half g_w16[57344];                // W0|Ws|lin_w in fp16
__device__ __align__(16) __half g_tmp[(size_t)Nn * Hd];      // h @ W (gather payload)
__device__ __align__(16) __half g_hall[(size_t)Ll * Nn * Hd];// per-layer h (JK)
__device__ int   g_is64;

#define SW(o) ((o) ^ (((o) >> 3) & 0x70))

// ---------------- mma/ldmatrix helpers ----------------
__device__ __forceinline__ uint32_t s2u(const void* p) {
    uint32_t a;
    asm("{ .reg .u64 t; cvta.to.shared.u64 t, %1; cvt.u32.u64 %0, t; }" : "=r"(a) : "l"(p));
    return a;
}
__device__ __forceinline__ void ldsm_x4(uint32_t& a0, uint32_t& a1, uint32_t& a2,
                                        uint32_t& a3, uint32_t addr) {
    asm volatile("ldmatrix.sync.aligned.m8n8.x4.shared.b16 {%0,%1,%2,%3},[%4];"
                 : "=r"(a0), "=r"(a1), "=r"(a2), "=r"(a3) : "r"(addr));
}
__device__ __forceinline__ void ldsm_x2t(uint32_t& b0, uint32_t& b1, uint32_t addr) {
    asm volatile("ldmatrix.sync.aligned.m8n8.x2.trans.shared.b16 {%0,%1},[%2];"
                 : "=r"(b0), "=r"(b1) : "r"(addr));
}
__device__ __forceinline__ void mma16816(float* d, uint32_t a0, uint32_t a1, uint32_t a2,
                                         uint32_t a3, uint32_t b0, uint32_t b1) {
    asm volatile(
        "mma.sync.aligned.m16n8k16.row.col.f32.f16.f16.f32 "
        "{%0,%1,%2,%3},{%4,%5,%6,%7},{%8,%9},{%0,%1,%2,%3};"
        : "+f"(d[0]), "+f"(d[1]), "+f"(d[2]), "+f"(d[3])
        : "r"(a0), "r"(a1), "r"(a2), "r"(a3), "r"(b0), "r"(b1));
}

// ---------------- dtype probe ----------------
__global__ void k_detect(const unsigned int* __restrict__ p) {
    __shared__ unsigned int s;
    if (threadIdx.x == 0) s = 0u;
    __syncthreads();
    unsigned int v = 0u;
    for (int e = threadIdx.x; e < 2048; e += 256) v |= p[2 * e + 1];
    atomicOr(&s, v);
    __syncthreads();
    if (threadIdx.x == 0) g_is64 = (s == 0u) ? 1 : 0;
}
__device__ __forceinline__ int ld_src(const int* p, int e) {
    return g_is64 ? p[2 * e] : p[e];
}
__device__ __forceinline__ int ld_dst(const int* p, int e) {
    return g_is64 ? p[2 * Ee + 2 * e] : p[Ee + e];
}

// ---------------- converts ----------------
__global__ void k_cvt_w(const float* __restrict__ W0, const float* __restrict__ Ws,
                        const float* __restrict__ lw) {
    int i = blockIdx.x * 256 + threadIdx.x;
    if (i >= 57344) return;
    float v;
    if (i < 8192) v = W0[i];
    else if (i < 36864) v = Ws[i - 8192];
    else v = lw[i - 36864];
    g_w16[i] = __float2half(v);
}
__global__ void k_cvt_x(const float* __restrict__ x) {
    int i = blockIdx.x * 256 + threadIdx.x;  // over float4s: N*128/4 = 3.2M
    if (i >= Nn * 32) return;
    float4 v = ((const float4*)x)[i];
    __half2* o = (__half2*)g_x16;
    o[2 * i]     = __floats2half2_rn(v.x, v.y);
    o[2 * i + 1] = __floats2half2_rn(v.z, v.w);
}

// ---------------- degree / CSR ----------------
__global__ void k_count(const int* __restrict__ ei) {
    int e = blockIdx.x * 256 + threadIdx.x;
    if (e < Ee) atomicAdd(&g_deg[ld_dst(ei, e)], 1);
}
__global__ void k_scan_block() {
    __shared__ int s[1024];
    int i = blockIdx.x * 1024 + threadIdx.x;
    int v = (i < Nn) ? g_deg[i] : 0;
    if (i < Nn) g_dis[i] = rsqrtf((float)(v + 1));
    s[threadIdx.x] = v;
    __syncthreads();
    for (int off = 1; off < 1024; off <<= 1) {
        int t = (threadIdx.x >= off) ? s[threadIdx.x - off] : 0;
        __syncthreads();
        s[threadIdx.x] += t;
        __syncthreads();
    }
    if (i < Nn) g_rowptr[i] = s[threadIdx.x] - v;
    if (threadIdx.x == 1023) g_bsum[blockIdx.x] = s[1023];
}
__global__ void k_add_off() {
    __shared__ int sb[128];
    int t = threadIdx.x;
    if (t < 128) sb[t] = (t < (int)blockIdx.x) ? g_bsum[t] : 0;
    __syncthreads();
    for (int off = 64; off > 0; off >>= 1) {
        if (t < off) sb[t] += sb[t + off];
        __syncthreads();
    }
    int base = sb[0];
    int i = blockIdx.x * 1024 + t;
    if (i < Nn) {
        int r = g_rowptr[i] + base;
        g_rowptr[i] = r;
        g_cursor[i] = r;
    }
    if (i == 0) g_rowptr[Nn] = Ee;
}
__global__ void k_fill(const int* __restrict__ ei) {
    int e = blockIdx.x * 256 + threadIdx.x;
    if (e >= Ee) return;
    int s = ld_src(ei, e);
    int d = ld_dst(ei, e);
    int p = atomicAdd(&g_cursor[d], 1);
    g_ew[p] = make_int2(s, __float_as_int(g_dis[s] * g_dis[d]));
}

// ---------------- tensor-core GEMM: C[N,64] = A[N,K] @ B[K,64], all fp16 ----------------
template <int K>
__global__ void k_gemm_tc(const __half* __restrict__ A, const __half* __restrict__ B,
                          __half2* __restrict__ C) {
    __shared__ __align__(16) uint8_t sA[(K / 64) * 16384];  // panels of 128 rows x 128B
    __shared__ __align__(16) uint8_t sB[K * 128];           // K rows x 128B
    const int row0 = blockIdx.x * 128;
    const int tid = threadIdx.x;
    constexpr int CPR = K / 8;  // 16B chunks per A row
    for (int ci = tid; ci < 128 * CPR; ci += 256) {
        int r = ci / CPR, c = ci % CPR;
        uint4 v = make_uint4(0, 0, 0, 0);
        if (row0 + r < Nn) v = ((const uint4*)(A + (size_t)(row0 + r) * K))[c];
        *(uint4*)(sA + (c >> 3) * 16384 + SW(r * 128 + (c & 7) * 16)) = v;
    }
    for (int ci = tid; ci < K * 8; ci += 256) {
        int r = ci >> 3, c = ci & 7;
        uint4 v = ((const uint4*)(B + r * 64))[c];
        *(uint4*)(sB + SW(r * 128 + c * 16)) = v;
    }
    __syncthreads();

    const int warp = tid >> 5, lane = tid & 31;
    const int m_local = warp * 16;
    const uint32_t sAu = s2u(sA), sBu = s2u(sB);
    const int arow = m_local + (lane & 15);
    const int acol16 = (lane >> 4) * 16;
    float acc[8][4];
#pragma unroll
    for (int i = 0; i < 8; i++)
#pragma unroll
        for (int j = 0; j < 4; j++) acc[i][j] = 0.f;

#pragma unroll
    for (int ks = 0; ks < K / 16; ks++) {
        int k0 = ks * 16;
        uint32_t a0, a1, a2, a3;
        ldsm_x4(a0, a1, a2, a3,
                sAu + (k0 >> 6) * 16384 + SW(arow * 128 + (k0 & 63) * 2 + acol16));
        uint32_t brow = sBu;
#pragma unroll
        for (int nt = 0; nt < 8; nt++) {
            uint32_t b0, b1;
            ldsm_x2t(b0, b1, brow + SW((k0 + (lane & 15)) * 128 + nt * 16));
            mma16816(acc[nt], a0, a1, a2, a3, b0, b1);
        }
    }
    const int g = lane >> 2, t4 = lane & 3;
    int r0 = row0 + m_local + g, r1 = r0 + 8;
    if (r0 < Nn) {
#pragma unroll
        for (int nt = 0; nt < 8; nt++)
            C[(size_t)r0 * 32 + nt * 4 + t4] = __floats2half2_rn(acc[nt][0], acc[nt][1]);
    }
    if (r1 < Nn) {
#pragma unroll
        for (int nt = 0; nt < 8; nt++)
            C[(size_t)r1 * 32 + nt * 4 + t4] = __floats2half2_rn(acc[nt][2], acc[nt][3]);
    }
}

// ------- JK tensor-core GEMM: out[N,40] = concat_l(h_l)[N,512] @ lw[512,40] + lin_b -------
__global__ void k_jk_tc(const __half* __restrict__ hall, const __half* __restrict__ lw,
                        const float* __restrict__ lin_b, float* __restrict__ out) {
    __shared__ __align__(16) uint8_t sA[16384];  // 128 rows x 128B (one slot)
    __shared__ __align__(16) uint8_t sB[8192];   // 64 k-rows x 128B (40 cols padded)
    const int row0 = blockIdx.x * 128;
    const int tid = threadIdx.x;
    const int warp = tid >> 5, lane = tid & 31;
    const int m_local = warp * 16;
    const uint32_t sAu = s2u(sA), sBu = s2u(sB);
    const int arow = m_local + (lane & 15);
    const int acol16 = (lane >> 4) * 16;
    float acc[5][4];
#pragma unroll
    for (int i = 0; i < 5; i++)
#pragma unroll
        for (int j = 0; j < 4; j++) acc[i][j] = 0.f;

    for (int slot = 0; slot < Ll; slot++) {
        for (int ci = tid; ci < 1024; ci += 256) {
            int r = ci >> 3, c = ci & 7;
            uint4 v = make_uint4(0, 0, 0, 0);
            if (row0 + r < Nn)
                v = ((const uint4*)(hall + ((size_t)slot * Nn + row0 + r) * 64))[c];
            *(uint4*)(sA + SW(r * 128 + c * 16)) = v;
        }
        for (int ci = tid; ci < 512; ci += 256) {
            int r = ci >> 3, c = ci & 7;
            uint4 v = make_uint4(0, 0, 0, 0);
            if (c < 5) v = ((const uint4*)(lw + (size_t)(slot * 64 + r) * OUTD))[c];
            *(uint4*)(sB + SW(r * 128 + c * 16)) = v;
        }
        __syncthreads();
#pragma unroll
        for (int ks = 0; ks < 4; ks++) {
            int k0 = ks * 16;
            uint32_t a0, a1, a2, a3;
            ldsm_x4(a0, a1, a2, a3, sAu + SW(arow * 128 + k0 * 2 + acol16));
#pragma unroll
            for (int nt = 0; nt < 5; nt++) {
                uint32_t b0, b1;
                ldsm_x2t(b0, b1, sBu + SW((k0 + (lane & 15)) * 128 + nt * 16));
                mma16816(acc[nt], a0, a1, a2, a3, b0, b1);
            }
        }
        __syncthreads();
    }
    const int g = lane >> 2, t4 = lane & 3;
    int r0 = row0 + m_local + g, r1 = r0 + 8;
#pragma unroll
    for (int nt = 0; nt < 5; nt++) {
        int c = nt * 8 + t4 * 2;
        float bl0 = lin_b[c], bl1 = lin_b[c + 1];
        if (r0 < Nn)
            *(float2*)&out[(size_t)r0 * OUTD + c] =
                make_float2(acc[nt][0] + bl0, acc[nt][1] + bl1);
        if (r1 < Nn)
            *(float2*)&out[(size_t)r1 * OUTD + c] =
                make_float2(acc[nt][2] + bl0, acc[nt][3] + bl1);
    }
}

// ---------------- sparse aggregation: hdst = relu(A_hat * tmp + b) ----------------
__global__ void k_aggregate(const float* __restrict__ bias, __half2* __restrict__ hdst) {
    int node = blockIdx.x * 8 + (threadIdx.x >> 5);
    if (node >= Nn) return;
    int lane = threadIdx.x & 31;
    const __half2* tp = (const __half2*)g_tmp;
    float ax = 0.f, ay = 0.f;
    int beg = g_rowptr[node], end = g_rowptr[node + 1];
    for (int j = beg; j < end; j++) {
        int2 e = __ldg(&g_ew[j]);
        float wt = __int_as_float(e.y);
        float2 v = __half22float2(tp[(size_t)e.x * 32 + lane]);
        ax += wt * v.x;
        ay += wt * v.y;
    }
    float d = g_dis[node];
    float sw = d * d;
    float2 v = __half22float2(tp[(size_t)node * 32 + lane]);
    ax += sw * v.x;
    ay += sw * v.y;
    ax += bias[2 * lane];
    ay += bias[2 * lane + 1];
    hdst[(size_t)node * 32 + lane] = __floats2half2_rn(fmaxf(ax, 0.f), fmaxf(ay, 0.f));
}

extern "C" void kernel_launch(void* const* d_in, const int* in_sizes, int n_in,
                              void* d_out, int out_size) {
    const float* x = nullptr;
    const float* W0 = nullptr;
    const float* Ws = nullptr;
    const float* bs = nullptr;
    const float* lin_w = nullptr;
    const float* lin_b = nullptr;
    const int*   ei = nullptr;
    for (int i = 0; i < n_in; i++) {
        switch (in_sizes[i]) {
            case 12800000: x     = (const float*)d_in[i]; break;
            case 8192:     W0    = (const float*)d_in[i]; break;
            case 28672:    Ws    = (const float*)d_in[i]; break;
            case 512:      bs    = (const float*)d_in[i]; break;
            case 20480:    lin_w = (const float*)d_in[i]; break;
            case 40:       lin_b = (const float*)d_in[i]; break;
            case 3200000:
            case 6400000:  ei    = (const int*)d_in[i];   break;
            default: break;
        }
    }
    if (!(x && W0 && Ws && bs && lin_w && lin_b && ei)) {
        x     = (const float*)d_in[0];
        W0    = (const float*)d_in[1];
        Ws    = (const float*)d_in[2];
        bs    = (const float*)d_in[3];
        lin_w = (const float*)d_in[4];
        lin_b = (const float*)d_in[5];
        ei    = (const int*)d_in[6];
    }
    float* out = (float*)d_out;

    // device-symbol addresses for host-side kernel args (R7 root cause)
    __half *x16_d, *w16_d, *tmp_d, *hall_d;
    int* deg_d;
    cudaGetSymbolAddress((void**)&x16_d, g_x16);
    cudaGetSymbolAddress((void**)&w16_d, g_w16);
    cudaGetSymbolAddress((void**)&tmp_d, g_tmp);
    cudaGetSymbolAddress((void**)&hall_d, g_hall);
    cudaGetSymbolAddress((void**)&deg_d, g_deg);

    cudaStreamCaptureStatus cst = cudaStreamCaptureStatusNone;
    cudaError_t qe = cudaStreamIsCapturing((cudaStream_t)0, &cst);
    bool capturing = (qe != cudaSuccess) || (cst != cudaStreamCaptureStatusNone);
    if (qe != cudaSuccess) (void)cudaGetLastError();

    const int NB = (Nn + 1023) / 1024;       // 98
    const int GEMM_GRID = (Nn + 127) / 128;  // 782
    const int AGG_GRID = (Nn + 7) / 8;

    // slot-5 (incl. memset) = k_gemm_tc<128> -> profiled next round
    k_detect<<<1, 256>>>((const unsigned int*)ei);                   // 1
    cudaMemsetAsync(deg_d, 0, Nn * sizeof(int), 0);                  // 2
    k_cvt_w<<<224, 256>>>(W0, Ws, lin_w);                            // 3
    k_cvt_x<<<(Nn * 32 + 255) / 256, 256>>>(x);                      // 4
    k_gemm_tc<128><<<GEMM_GRID, 256>>>(x16_d, w16_d, (__half2*)tmp_d);  // 5 <- profiled
    k_count<<<(Ee + 255) / 256, 256>>>(ei);                          // 6
    k_scan_block<<<NB, 1024>>>();                                    // 7
    k_add_off<<<NB, 1024>>>();                                       // 8
    k_fill<<<(Ee + 255) / 256, 256>>>(ei);                           // 9

    for (int l = 0; l < Ll; l++) {
        k_aggregate<<<AGG_GRID, 256>>>(bs + l * Hd,
                                       (__half2*)(hall_d + (size_t)l * Nn * Hd));
        if (l < Ll - 1)
            k_gemm_tc<64><<<GEMM_GRID, 256>>>(hall_d + (size_t)l * Nn * Hd,
                                              w16_d + 8192 + (size_t)l * 4096,
                                              (__half2*)tmp_d);
    }
    k_jk_tc<<<GEMM_GRID, 256>>>(hall_d, w16_d + 36864, lin_b, out);

    // -------- zero-output tripwire (correctness call only; never during capture) --------
    if (!capturing) {
        static float ho[8];
        cudaMemcpyAsync(ho, out, 8 * sizeof(float), cudaMemcpyDeviceToHost, 0);
        cudaError_t qs = cudaErrorNotReady;
        for (long it = 0; it < 4000000000L; it++) {
            qs = cudaStreamQuery((cudaStream_t)0);
            if (qs != cudaErrorNotReady) break;
        }
        float mx = 0.f;
        for (int i = 0; i < 8; i++) mx = fmaxf(mx, fabsf(ho[i]));
        if (qs != cudaSuccess || mx < 1e-6f) {
            fprintf(stderr, "[diag] TRIPWIRE mx=%g q=%s out=%g %g %g %g\n", mx,
                    cudaGetErrorName(qs), ho[0], ho[1], ho[2], ho[3]);
            fflush(stderr);
            abort();
        }
    }
}

// round 14
// speedup vs baseline: 2.2401x; 1.1949x over previous
#include <cuda_runtime.h>
#include <cuda_fp16.h>
#include <cstdio>
#include <cstdlib>
#include <cstdint>
#include <cmath>

#define Nn   100000
#define Ee   1600000
#define Hd   64
#define Ll   8
#define OUTD 40

// ---------------- scratch (static device globals; no allocation) ----------------
__device__ int   g_deg[Nn];
__device__ float g_dis[Nn];
__device__ int   g_rowptr[Nn + 1];
__device__ int   g_cursor[Nn];
__device__ __align__(16) int2   g_ew[Ee];                    // {src, float_bits(norm)}
__device__ int   g_bsum[128];
__device__ __align__(16) __half g_w16[57344];                // W0|Ws|lin_w in fp16
__device__ __align__(16) __half g_tmp[(size_t)Nn * Hd];      // h @ W (gather payload)
__device__ __align__(16) __half g_hall[(size_t)Ll * Nn * Hd];// per-layer h (JK)
__device__ int   g_is64;

#define SW(o) ((o) ^ (((o) >> 3) & 0x70))

// ---------------- mma/ldmatrix helpers ----------------
__device__ __forceinline__ uint32_t s2u(const void* p) {
    uint32_t a;
    asm("{ .reg .u64 t; cvta.to.shared.u64 t, %1; cvt.u32.u64 %0, t; }" : "=r"(a) : "l"(p));
    return a;
}
__device__ __forceinline__ void ldsm_x4(uint32_t& a0, uint32_t& a1, uint32_t& a2,
                                        uint32_t& a3, uint32_t addr) {
    asm volatile("ldmatrix.sync.aligned.m8n8.x4.shared.b16 {%0,%1,%2,%3},[%4];"
                 : "=r"(a0), "=r"(a1), "=r"(a2), "=r"(a3) : "r"(addr));
}
__device__ __forceinline__ void ldsm_x2t(uint32_t& b0, uint32_t& b1, uint32_t addr) {
    asm volatile("ldmatrix.sync.aligned.m8n8.x2.trans.shared.b16 {%0,%1},[%2];"
                 : "=r"(b0), "=r"(b1) : "r"(addr));
}
__device__ __forceinline__ void mma16816(float* d, uint32_t a0, uint32_t a1, uint32_t a2,
                                         uint32_t a3, uint32_t b0, uint32_t b1) {
    asm volatile(
        "mma.sync.aligned.m16n8k16.row.col.f32.f16.f16.f32 "
        "{%0,%1,%2,%3},{%4,%5,%6,%7},{%8,%9},{%0,%1,%2,%3};"
        : "+f"(d[0]), "+f"(d[1]), "+f"(d[2]), "+f"(d[3])
        : "r"(a0), "r"(a1), "r"(a2), "r"(a3), "r"(b0), "r"(b1));
}

// ---------------- dtype probe ----------------
__global__ void k_detect(const unsigned int* __restrict__ p) {
    __shared__ unsigned int s;
    if (threadIdx.x == 0) s = 0u;
    __syncthreads();
    unsigned int v = 0u;
    for (int e = threadIdx.x; e < 2048; e += 256) v |= p[2 * e + 1];
    atomicOr(&s, v);
    __syncthreads();
    if (threadIdx.x == 0) g_is64 = (s == 0u) ? 1 : 0;
}
__device__ __forceinline__ int ld_src(const int* p, int e) {
    return g_is64 ? p[2 * e] : p[e];
}
__device__ __forceinline__ int ld_dst(const int* p, int e) {
    return g_is64 ? p[2 * Ee + 2 * e] : p[Ee + e];
}

// ---------------- weight convert (fp32 -> fp16) ----------------
__global__ void k_cvt_w(const float* __restrict__ W0, const float* __restrict__ Ws,
                        const float* __restrict__ lw) {
    int i = blockIdx.x * 256 + threadIdx.x;
    if (i >= 57344) return;
    float v;
    if (i < 8192) v = W0[i];
    else if (i < 36864) v = Ws[i - 8192];
    else v = lw[i - 36864];
    g_w16[i] = __float2half(v);
}

// ---------------- degree / CSR ----------------
__global__ void k_count(const int* __restrict__ ei) {
    int e = blockIdx.x * 256 + threadIdx.x;
    if (e < Ee) atomicAdd(&g_deg[ld_dst(ei, e)], 1);
}
__global__ void k_scan_block() {
    __shared__ int s[1024];
    int i = blockIdx.x * 1024 + threadIdx.x;
    int v = (i < Nn) ? g_deg[i] : 0;
    if (i < Nn) g_dis[i] = rsqrtf((float)(v + 1));
    s[threadIdx.x] = v;
    __syncthreads();
    for (int off = 1; off < 1024; off <<= 1) {
        int t = (threadIdx.x >= off) ? s[threadIdx.x - off] : 0;
        __syncthreads();
        s[threadIdx.x] += t;
        __syncthreads();
    }
    if (i < Nn) g_rowptr[i] = s[threadIdx.x] - v;
    if (threadIdx.x == 1023) g_bsum[blockIdx.x] = s[1023];
}
__global__ void k_add_off() {
    __shared__ int sb[128];
    int t = threadIdx.x;
    if (t < 128) sb[t] = (t < (int)blockIdx.x) ? g_bsum[t] : 0;
    __syncthreads();
    for (int off = 64; off > 0; off >>= 1) {
        if (t < off) sb[t] += sb[t + off];
        __syncthreads();
    }
    int base = sb[0];
    int i = blockIdx.x * 1024 + t;
    if (i < Nn) {
        int r = g_rowptr[i] + base;
        g_rowptr[i] = r;
        g_cursor[i] = r;
    }
    if (i == 0) g_rowptr[Nn] = Ee;
}
__global__ void k_fill(const int* __restrict__ ei) {
    int e = blockIdx.x * 256 + threadIdx.x;
    if (e >= Ee) return;
    int s = ld_src(ei, e);
    int d = ld_dst(ei, e);
    int p = atomicAdd(&g_cursor[d], 1);
    g_ew[p] = make_int2(s, __float_as_int(g_dis[s] * g_dis[d]));
}

// ------- GEMM0 (fused cvt): tmp[fp16] = fp16(x[N,128]) @ W0_16[128,64] -------
__global__ void k_gemm0_tc(const float* __restrict__ A, const __half* __restrict__ B,
                           __half2* __restrict__ C) {
    __shared__ __align__(16) uint8_t sA[2 * 16384];  // 2 panels: 128 rows x 128B
    __shared__ __align__(16) uint8_t sB[128 * 128];
    const int row0 = blockIdx.x * 128;
    const int tid = threadIdx.x;
    // A: load fp32, convert to fp16, swizzled store (8B granules)
    for (int ci = tid; ci < 128 * 32; ci += 256) {
        int r = ci >> 5, c4 = ci & 31;
        float4 v = make_float4(0.f, 0.f, 0.f, 0.f);
        if (row0 + r < Nn) v = ((const float4*)(A + (size_t)(row0 + r) * 128))[c4];
        __half2 h0 = __floats2half2_rn(v.x, v.y);
        __half2 h1 = __floats2half2_rn(v.z, v.w);
        uint2 u = make_uint2(*(uint32_t*)&h0, *(uint32_t*)&h1);
        *(uint2*)(sA + (c4 >> 4) * 16384 + SW(r * 128 + (c4 & 15) * 8)) = u;
    }
    for (int ci = tid; ci < 128 * 8; ci += 256) {
        int r = ci >> 3, c = ci & 7;
        uint4 v = ((const uint4*)(B + r * 64))[c];
        *(uint4*)(sB + SW(r * 128 + c * 16)) = v;
    }
    __syncthreads();

    const int warp = tid >> 5, lane = tid & 31;
    const int m_local = warp * 16;
    const uint32_t sAu = s2u(sA), sBu = s2u(sB);
    const int arow = m_local + (lane & 15);
    const int acol16 = (lane >> 4) * 16;
    float acc[8][4];
#pragma unroll
    for (int i = 0; i < 8; i++)
#pragma unroll
        for (int j = 0; j < 4; j++) acc[i][j] = 0.f;

#pragma unroll
    for (int ks = 0; ks < 8; ks++) {
        int k0 = ks * 16;
        uint32_t a0, a1, a2, a3;
        ldsm_x4(a0, a1, a2, a3,
                sAu + (k0 >> 6) * 16384 + SW(arow * 128 + (k0 & 63) * 2 + acol16));
#pragma unroll
        for (int nt = 0; nt < 8; nt++) {
            uint32_t b0, b1;
            ldsm_x2t(b0, b1, sBu + SW((k0 + (lane & 15)) * 128 + nt * 16));
            mma16816(acc[nt], a0, a1, a2, a3, b0, b1);
        }
    }
    const int g = lane >> 2, t4 = lane & 3;
    int r0 = row0 + m_local + g, r1 = r0 + 8;
    if (r0 < Nn) {
#pragma unroll
        for (int nt = 0; nt < 8; nt++)
            C[(size_t)r0 * 32 + nt * 4 + t4] = __floats2half2_rn(acc[nt][0], acc[nt][1]);
    }
    if (r1 < Nn) {
#pragma unroll
        for (int nt = 0; nt < 8; nt++)
            C[(size_t)r1 * 32 + nt * 4 + t4] = __floats2half2_rn(acc[nt][2], acc[nt][3]);
    }
}

// ---------------- tensor-core GEMM: C[N,64] = A[N,64] @ B[64,64], fp16 ----------------
__global__ void k_gemm_tc(const __half* __restrict__ A, const __half* __restrict__ B,
                          __half2* __restrict__ C) {
    __shared__ __align__(16) uint8_t sA[16384];
    __shared__ __align__(16) uint8_t sB[64 * 128];
    const int row0 = blockIdx.x * 128;
    const int tid = threadIdx.x;
    for (int ci = tid; ci < 128 * 8; ci += 256) {
        int r = ci >> 3, c = ci & 7;
        uint4 v = make_uint4(0, 0, 0, 0);
        if (row0 + r < Nn) v = ((const uint4*)(A + (size_t)(row0 + r) * 64))[c];
        *(uint4*)(sA + SW(r * 128 + c * 16)) = v;
    }
    for (int ci = tid; ci < 64 * 8; ci += 256) {
        int r = ci >> 3, c = ci & 7;
        uint4 v = ((const uint4*)(B + r * 64))[c];
        *(uint4*)(sB + SW(r * 128 + c * 16)) = v;
    }
    __syncthreads();

    const int warp = tid >> 5, lane = tid & 31;
    const int m_local = warp * 16;
    const uint32_t sAu = s2u(sA), sBu = s2u(sB);
    const int arow = m_local + (lane & 15);
    const int acol16 = (lane >> 4) * 16;
    float acc[8][4];
#pragma unroll
    for (int i = 0; i < 8; i++)
#pragma unroll
        for (int j = 0; j < 4; j++) acc[i][j] = 0.f;

#pragma unroll
    for (int ks = 0; ks < 4; ks++) {
        int k0 = ks * 16;
        uint32_t a0, a1, a2, a3;
        ldsm_x4(a0, a1, a2, a3, sAu + SW(arow * 128 + k0 * 2 + acol16));
#pragma unroll
        for (int nt = 0; nt < 8; nt++) {
            uint32_t b0, b1;
            ldsm_x2t(b0, b1, sBu + SW((k0 + (lane & 15)) * 128 + nt * 16));
            mma16816(acc[nt], a0, a1, a2, a3, b0, b1);
        }
    }
    const int g = lane >> 2, t4 = lane & 3;
    int r0 = row0 + m_local + g, r1 = r0 + 8;
    if (r0 < Nn) {
#pragma unroll
        for (int nt = 0; nt < 8; nt++)
            C[(size_t)r0 * 32 + nt * 4 + t4] = __floats2half2_rn(acc[nt][0], acc[nt][1]);
    }
    if (r1 < Nn) {
#pragma unroll
        for (int nt = 0; nt < 8; nt++)
            C[(size_t)r1 * 32 + nt * 4 + t4] = __floats2half2_rn(acc[nt][2], acc[nt][3]);
    }
}

// ------- JK tensor-core GEMM: out[N,40] = concat_l(h_l)[N,512] @ lw[512,40] + lin_b -------
__global__ void k_jk_tc(const __half* __restrict__ hall, const __half* __restrict__ lw,
                        const float* __restrict__ lin_b, float* __restrict__ out) {
    __shared__ __align__(16) uint8_t sA[16384];
    __shared__ __align__(16) uint8_t sB[8192];
    const int row0 = blockIdx.x * 128;
    const int tid = threadIdx.x;
    const int warp = tid >> 5, lane = tid & 31;
    const int m_local = warp * 16;
    const uint32_t sAu = s2u(sA), sBu = s2u(sB);
    const int arow = m_local + (lane & 15);
    const int acol16 = (lane >> 4) * 16;
    float acc[5][4];
#pragma unroll
    for (int i = 0; i < 5; i++)
#pragma unroll
        for (int j = 0; j < 4; j++) acc[i][j] = 0.f;

    for (int slot = 0; slot < Ll; slot++) {
        for (int ci = tid; ci < 1024; ci += 256) {
            int r = ci >> 3, c = ci & 7;
            uint4 v = make_uint4(0, 0, 0, 0);
            if (row0 + r < Nn)
                v = ((const uint4*)(hall + ((size_t)slot * Nn + row0 + r) * 64))[c];
            *(uint4*)(sA + SW(r * 128 + c * 16)) = v;
        }
        for (int ci = tid; ci < 512; ci += 256) {
            int r = ci >> 3, c = ci & 7;
            uint4 v = make_uint4(0, 0, 0, 0);
            if (c < 5) v = ((const uint4*)(lw + (size_t)(slot * 64 + r) * OUTD))[c];
            *(uint4*)(sB + SW(r * 128 + c * 16)) = v;
        }
        __syncthreads();
#pragma unroll
        for (int ks = 0; ks < 4; ks++) {
            int k0 = ks * 16;
            uint32_t a0, a1, a2, a3;
            ldsm_x4(a0, a1, a2, a3, sAu + SW(arow * 128 + k0 * 2 + acol16));
#pragma unroll
            for (int nt = 0; nt < 5; nt++) {
                uint32_t b0, b1;
                ldsm_x2t(b0, b1, sBu + SW((k0 + (lane & 15)) * 128 + nt * 16));
                mma16816(acc[nt], a0, a1, a2, a3, b0, b1);
            }
        }
        __syncthreads();
    }
    const int g = lane >> 2, t4 = lane & 3;
    int r0 = row0 + m_local + g, r1 = r0 + 8;
#pragma unroll
    for (int nt = 0; nt < 5; nt++) {
        int c = nt * 8 + t4 * 2;
        float bl0 = lin_b[c], bl1 = lin_b[c + 1];
        if (r0 < Nn)
            *(float2*)&out[(size_t)r0 * OUTD + c] =
                make_float2(acc[nt][0] + bl0, acc[nt][1] + bl1);
        if (r1 < Nn)
            *(float2*)&out[(size_t)r1 * OUTD + c] =
                make_float2(acc[nt][2] + bl0, acc[nt][3] + bl1);
    }
}

// ------ aggregation: 4 nodes/warp, 8 lanes/node, 16B (8 halves) per lane ------
__global__ void k_aggregate(const float* __restrict__ bias, uint4* __restrict__ hdst) {
    int warp = (blockIdx.x * 256 + threadIdx.x) >> 5;
    int lane = threadIdx.x & 31;
    int node = warp * 4 + (lane >> 3);
    if (node >= Nn) return;
    int fl = lane & 7;  // 16B chunk within 128B row
    const uint4* tp = (const uint4*)g_tmp;
    float a0 = 0.f, a1 = 0.f, a2 = 0.f, a3 = 0.f, a4 = 0.f, a5 = 0.f, a6 = 0.f, a7 = 0.f;
    int beg = g_rowptr[node], end = g_rowptr[node + 1];
    for (int j = beg; j < end; j++) {
        int2 e = __ldg(&g_ew[j]);
        float wt = __int_as_float(e.y);
        uint4 v = __ldg(&tp[(size_t)e.x * 8 + fl]);
        float2 p0 = __half22float2(*(__half2*)&v.x);
        float2 p1 = __half22float2(*(__half2*)&v.y);
        float2 p2 = __half22float2(*(__half2*)&v.z);
        float2 p3 = __half22float2(*(__half2*)&v.w);
        a0 += wt * p0.x; a1 += wt * p0.y;
        a2 += wt * p1.x; a3 += wt * p1.y;
        a4 += wt * p2.x; a5 += wt * p2.y;
        a6 += wt * p3.x; a7 += wt * p3.y;
    }
    float d = g_dis[node];
    float sw = d * d;  // self-loop norm
    {
        uint4 v = tp[(size_t)node * 8 + fl];
        float2 p0 = __half22float2(*(__half2*)&v.x);
        float2 p1 = __half22float2(*(__half2*)&v.y);
        float2 p2 = __half22float2(*(__half2*)&v.z);
        float2 p3 = __half22float2(*(__half2*)&v.w);
        a0 += sw * p0.x; a1 += sw * p0.y;
        a2 += sw * p1.x; a3 += sw * p1.y;
        a4 += sw * p2.x; a5 += sw * p2.y;
        a6 += sw * p3.x; a7 += sw * p3.y;
    }
    const float4 b0 = *(const float4*)&bias[fl * 8];
    const float4 b1 = *(const float4*)&bias[fl * 8 + 4];
    __half2 h0 = __floats2half2_rn(fmaxf(a0 + b0.x, 0.f), fmaxf(a1 + b0.y, 0.f));
    __half2 h1 = __floats2half2_rn(fmaxf(a2 + b0.z, 0.f), fmaxf(a3 + b0.w, 0.f));
    __half2 h2 = __floats2half2_rn(fmaxf(a4 + b1.x, 0.f), fmaxf(a5 + b1.y, 0.f));
    __half2 h3 = __floats2half2_rn(fmaxf(a6 + b1.z, 0.f), fmaxf(a7 + b1.w, 0.f));
    hdst[(size_t)node * 8 + fl] =
        make_uint4(*(uint32_t*)&h0, *(uint32_t*)&h1, *(uint32_t*)&h2, *(uint32_t*)&h3);
}

extern "C" void kernel_launch(void* const* d_in, const int* in_sizes, int n_in,
                              void* d_out, int out_size) {
    const float* x = nullptr;
    const float* W0 = nullptr;
    const float* Ws = nullptr;
    const float* bs = nullptr;
    const float* lin_w = nullptr;
    const float* lin_b = nullptr;
    const int*   ei = nullptr;
    for (int i = 0; i < n_in; i++) {
        switch (in_sizes[i]) {
            case 12800000: x     = (const float*)d_in[i]; break;
            case 8192:     W0    = (const float*)d_in[i]; break;
            case 28672:    Ws    = (const float*)d_in[i]; break;
            case 512:      bs    = (const float*)d_in[i]; break;
            case 20480:    lin_w = (const float*)d_in[i]; break;
            case 40:       lin_b = (const float*)d_in[i]; break;
            case 3200000:
            case 6400000:  ei    = (const int*)d_in[i];   break;
            default: break;
        }
    }
    if (!(x && W0 && Ws && bs && lin_w && lin_b && ei)) {
        x     = (const float*)d_in[0];
        W0    = (const float*)d_in[1];
        Ws    = (const float*)d_in[2];
        bs    = (const float*)d_in[3];
        lin_w = (const float*)d_in[4];
        lin_b = (const float*)d_in[5];
        ei    = (const int*)d_in[6];
    }
    float* out = (float*)d_out;

    // device-symbol addresses for host-side kernel args (R7 root cause)
    __half *w16_d, *tmp_d, *hall_d;
    int* deg_d;
    cudaGetSymbolAddress((void**)&w16_d, g_w16);
    cudaGetSymbolAddress((void**)&tmp_d, g_tmp);
    cudaGetSymbolAddress((void**)&hall_d, g_hall);
    cudaGetSymbolAddress((void**)&deg_d, g_deg);

    cudaStreamCaptureStatus cst = cudaStreamCaptureStatusNone;
    cudaError_t qe = cudaStreamIsCapturing((cudaStream_t)0, &cst);
    bool capturing = (qe != cudaSuccess) || (cst != cudaStreamCaptureStatusNone);
    if (qe != cudaSuccess) (void)cudaGetLastError();

    const int NB = (Nn + 1023) / 1024;       // 98
    const int GEMM_GRID = (Nn + 127) / 128;  // 782
    const int AGG_GRID = (Nn + 31) / 32;     // 4 nodes/warp * 8 warps/block

    k_detect<<<1, 256>>>((const unsigned int*)ei);                   // 1
    cudaMemsetAsync(deg_d, 0, Nn * sizeof(int), 0);                  // 2
    k_cvt_w<<<224, 256>>>(W0, Ws, lin_w);                            // 3
    k_count<<<(Ee + 255) / 256, 256>>>(ei);                          // 4
    k_gemm0_tc<<<GEMM_GRID, 256>>>(x, w16_d, (__half2*)tmp_d);       // 5 <- profiled
    k_scan_block<<<NB, 1024>>>();                                    // 6
    k_add_off<<<NB, 1024>>>();                                       // 7
    k_fill<<<(Ee + 255) / 256, 256>>>(ei);                           // 8

    for (int l = 0; l < Ll; l++) {
        k_aggregate<<<AGG_GRID, 256>>>(bs + l * Hd,
                                       (uint4*)(hall_d + (size_t)l * Nn * Hd));
        if (l < Ll - 1)
            k_gemm_tc<<<GEMM_GRID, 256>>>(hall_d + (size_t)l * Nn * Hd,
                                          w16_d + 8192 + (size_t)l * 4096,
                                          (__half2*)tmp_d);
    }
    k_jk_tc<<<GEMM_GRID, 256>>>(hall_d, w16_d + 36864, lin_b, out);

    // -------- zero-output tripwire (correctness call only; never during capture) --------
    if (!capturing) {
        static float ho[8];
        cudaMemcpyAsync(ho, out, 8 * sizeof(float), cudaMemcpyDeviceToHost, 0);
        cudaError_t qs = cudaErrorNotReady;
        for (long it = 0; it < 4000000000L; it++) {
            qs = cudaStreamQuery((cudaStream_t)0);
            if (qs != cudaErrorNotReady) break;
        }
        float mx = 0.f;
        for (int i = 0; i < 8; i++) mx = fmaxf(mx, fabsf(ho[i]));
        if (qs != cudaSuccess || mx < 1e-6f) {
            fprintf(stderr, "[diag] TRIPWIRE mx=%g q=%s out=%g %g %g %g\n", mx,
                    cudaGetErrorName(qs), ho[0], ho[1], ho[2], ho[3]);
            fflush(stderr);
            abort();
        }
    }
}